// round 12
// baseline (speedup 1.0000x reference)
#include <cuda_runtime.h>
#include <cuda_bf16.h>

#define BB 8192
#define DD 512
#define W1 128          // phase-1 candidate window
#define W2 2048         // phase-2a candidate window
#define BM 128
#define BK 16
#define NCH (DD / BK)   // 32 k-chunks
#define BK2 32
#define NCH2 (DD / BK2) // 16 k-chunks (phase2a)
#define P1 132          // phase1 padded smem row
#define P2A 68          // phase2 pad (64 + 4)
#define CH2B 64         // phase2b column chunk
#define NCH2B ((BB - W1 - W2) / CH2B)   // 94 chunks

// -------- scratch (device globals; no allocation allowed) --------
__device__ float g_inva[BB];
__device__ float g_invt[BB];
__device__ float g_invc[BB];
__device__ float g_sm[BB];
__device__ float g_smcr[BB];
__device__ float g_mcr[BB];
__device__ unsigned long long g_best[4][BB];
__device__ int g_cnt[4];
__device__ int g_list[4][BB];
__device__ int g_cnt2[4];
__device__ int g_list2[4][BB];
__device__ int g_tick2a[4];
__device__ int g_tickb;

static __device__ __forceinline__ unsigned long long umin64(unsigned long long a,
                                                            unsigned long long b) {
    return a < b ? a : b;
}

static __device__ __forceinline__ void pass_ptrs(
    int pass, const float* margin, const float* img, const float* txt, const float* cr,
    const float*& A, const float*& Bm, const float*& iA, const float*& iB,
    const float*& dg, const float*& mg) {
    switch (pass) {
        case 0: A = img; Bm = txt; iA = g_inva; iB = g_invt; dg = g_sm;   mg = margin; break;
        case 1: A = txt; Bm = img; iA = g_invt; iB = g_inva; dg = g_sm;   mg = margin; break;
        case 2: A = img; Bm = cr;  iA = g_inva; iB = g_invc; dg = g_smcr; mg = g_mcr;  break;
        default:A = cr;  Bm = img; iA = g_invc; iB = g_inva; dg = g_smcr; mg = g_mcr;  break;
    }
}

// -------- kernel 1: norms, diag sims, margin_cr, state reset ----------------
__global__ __launch_bounds__(256) void prep_kernel(
    const float* __restrict__ img, const float* __restrict__ txt,
    const float* __restrict__ cr, const float* __restrict__ margin,
    const int* __restrict__ aflag) {
    int row = blockIdx.x * 8 + (threadIdx.x >> 5);
    int lane = threadIdx.x & 31;
    const float4* pi = (const float4*)(img + (size_t)row * DD);
    const float4* pt = (const float4*)(txt + (size_t)row * DD);
    const float4* pc = (const float4*)(cr + (size_t)row * DD);

    float sii = 0.f, stt = 0.f, scc = 0.f, sit = 0.f, sic = 0.f;
#pragma unroll
    for (int e = 0; e < 4; e++) {
        float4 vi = pi[lane + 32 * e];
        float4 vt = pt[lane + 32 * e];
        float4 vc = pc[lane + 32 * e];
        sii += vi.x * vi.x + vi.y * vi.y + vi.z * vi.z + vi.w * vi.w;
        stt += vt.x * vt.x + vt.y * vt.y + vt.z * vt.z + vt.w * vt.w;
        scc += vc.x * vc.x + vc.y * vc.y + vc.z * vc.z + vc.w * vc.w;
        sit += vi.x * vt.x + vi.y * vt.y + vi.z * vt.z + vi.w * vt.w;
        sic += vi.x * vc.x + vi.y * vc.y + vi.z * vc.z + vi.w * vc.w;
    }
#pragma unroll
    for (int off = 16; off; off >>= 1) {
        sii += __shfl_xor_sync(0xFFFFFFFFu, sii, off);
        stt += __shfl_xor_sync(0xFFFFFFFFu, stt, off);
        scc += __shfl_xor_sync(0xFFFFFFFFu, scc, off);
        sit += __shfl_xor_sync(0xFFFFFFFFu, sit, off);
        sic += __shfl_xor_sync(0xFFFFFFFFu, sic, off);
    }
    if (lane == 0) {
        float inva = 1.f / (sqrtf(sii) + 1e-8f);
        float invt = 1.f / (sqrtf(stt) + 1e-8f);
        float invc = 1.f / (sqrtf(scc) + 1e-8f);
        g_inva[row] = inva; g_invt[row] = invt; g_invc[row] = invc;
        float sm = sit * inva * invt;
        float smcr = sic * inva * invc;
        g_sm[row] = sm;
        g_smcr[row] = smcr;
        float mrg = margin[row];
        float mcr;
        if (*aflag) {
            float lam = fminf(fabsf(smcr) / fabsf(sm), 1.f);
            mcr = (lam + 1.f) * mrg * 0.5f;
        } else {
            mcr = mrg * 0.5f;
        }
        g_mcr[row] = mcr;
    }
    if (blockIdx.x == 0 && threadIdx.x < 4) {
        g_cnt[threadIdx.x] = 0;
        g_cnt2[threadIdx.x] = 0;
        g_tick2a[threadIdx.x] = 0;
        if (threadIdx.x == 0) g_tickb = 0;
    }
}

// -------- kernel 2: phase-1 128x128 strip GEMM (16x4 microtile) + collect ---
__global__ __launch_bounds__(256, 2) void phase1_kernel(
    const float* __restrict__ img, const float* __restrict__ txt,
    const float* __restrict__ cr, const float* __restrict__ margin,
    const int* __restrict__ labels, const int* __restrict__ aflag) {
    __shared__ __align__(16) float As[2][BK * P1];
    __shared__ __align__(16) float Bs[2][BK * P1];
    __shared__ unsigned long long sbest[BM];

    int pass = blockIdx.y;
    const float *A, *Bm, *iA, *iB, *dg, *mg;
    pass_ptrs(pass, margin, img, txt, cr, A, Bm, iA, iB, dg, mg);

    int rowStart = blockIdx.x * BM;
    int tid = threadIdx.x;
    int tx = tid & 31;        // col group: 4 cols at 4*tx
    int ty = tid >> 5;        // row group: 16 rows at 16*ty

    if (tid < BM) sbest[tid] = ~0ull;

    unsigned long long acc[8][4];
#pragma unroll
    for (int i = 0; i < 8; i++)
#pragma unroll
        for (int j = 0; j < 4; j++) acc[i][j] = 0ull;

    int r0 = tid >> 2;
    int kk = (tid & 3) << 2;

    float iA0 = iA[rowStart + r0];
    float iA1 = iA[rowStart + r0 + 64];
    float iB0 = iB[r0];
    float iB1 = iB[r0 + 64];
    const float* aRow0 = A + (size_t)(rowStart + r0) * DD + kk;
    const float* aRow1 = A + (size_t)(rowStart + r0 + 64) * DD + kk;
    const float* bRow0 = Bm + (size_t)r0 * DD + kk;
    const float* bRow1 = Bm + (size_t)(r0 + 64) * DD + kk;

    float4 pa0 = *(const float4*)aRow0;
    float4 pa1 = *(const float4*)aRow1;
    float4 pb0 = *(const float4*)bRow0;
    float4 pb1 = *(const float4*)bRow1;

    {
        float* as = As[0]; float* bs = Bs[0];
        as[(kk + 0) * P1 + r0] = pa0.x * iA0; as[(kk + 1) * P1 + r0] = pa0.y * iA0;
        as[(kk + 2) * P1 + r0] = pa0.z * iA0; as[(kk + 3) * P1 + r0] = pa0.w * iA0;
        as[(kk + 0) * P1 + r0 + 64] = pa1.x * iA1; as[(kk + 1) * P1 + r0 + 64] = pa1.y * iA1;
        as[(kk + 2) * P1 + r0 + 64] = pa1.z * iA1; as[(kk + 3) * P1 + r0 + 64] = pa1.w * iA1;
        bs[(kk + 0) * P1 + r0] = pb0.x * iB0; bs[(kk + 1) * P1 + r0] = pb0.y * iB0;
        bs[(kk + 2) * P1 + r0] = pb0.z * iB0; bs[(kk + 3) * P1 + r0] = pb0.w * iB0;
        bs[(kk + 0) * P1 + r0 + 64] = pb1.x * iB1; bs[(kk + 1) * P1 + r0 + 64] = pb1.y * iB1;
        bs[(kk + 2) * P1 + r0 + 64] = pb1.z * iB1; bs[(kk + 3) * P1 + r0 + 64] = pb1.w * iB1;
    }
    __syncthreads();

    for (int c = 0; c < NCH; c++) {
        int cur = c & 1;
        bool more = (c + 1 < NCH);
        if (more) {
            int kn = (c + 1) * BK;
            pa0 = *(const float4*)(aRow0 + kn);
            pa1 = *(const float4*)(aRow1 + kn);
            pb0 = *(const float4*)(bRow0 + kn);
            pb1 = *(const float4*)(bRow1 + kn);
        }
        const float* as = As[cur];
        const float* bs = Bs[cur];
#pragma unroll
        for (int k = 0; k < BK; k++) {
            ulonglong2 q0 = *(const ulonglong2*)&as[k * P1 + (ty << 4)];
            ulonglong2 q1 = *(const ulonglong2*)&as[k * P1 + (ty << 4) + 4];
            ulonglong2 q2 = *(const ulonglong2*)&as[k * P1 + (ty << 4) + 8];
            ulonglong2 q3 = *(const ulonglong2*)&as[k * P1 + (ty << 4) + 12];
            float4 bv = *(const float4*)&bs[k * P1 + (tx << 2)];
            unsigned long long bd0, bd1, bd2, bd3;
            asm("mov.b64 %0, {%1, %1};" : "=l"(bd0) : "f"(bv.x));
            asm("mov.b64 %0, {%1, %1};" : "=l"(bd1) : "f"(bv.y));
            asm("mov.b64 %0, {%1, %1};" : "=l"(bd2) : "f"(bv.z));
            asm("mov.b64 %0, {%1, %1};" : "=l"(bd3) : "f"(bv.w));
            unsigned long long ap[8] = {q0.x, q0.y, q1.x, q1.y, q2.x, q2.y, q3.x, q3.y};
#pragma unroll
            for (int p = 0; p < 8; p++) {
                asm("fma.rn.f32x2 %0, %1, %2, %0;" : "+l"(acc[p][0]) : "l"(ap[p]), "l"(bd0));
                asm("fma.rn.f32x2 %0, %1, %2, %0;" : "+l"(acc[p][1]) : "l"(ap[p]), "l"(bd1));
                asm("fma.rn.f32x2 %0, %1, %2, %0;" : "+l"(acc[p][2]) : "l"(ap[p]), "l"(bd2));
                asm("fma.rn.f32x2 %0, %1, %2, %0;" : "+l"(acc[p][3]) : "l"(ap[p]), "l"(bd3));
            }
        }
        if (more) {
            float* asn = As[cur ^ 1]; float* bsn = Bs[cur ^ 1];
            asn[(kk + 0) * P1 + r0] = pa0.x * iA0; asn[(kk + 1) * P1 + r0] = pa0.y * iA0;
            asn[(kk + 2) * P1 + r0] = pa0.z * iA0; asn[(kk + 3) * P1 + r0] = pa0.w * iA0;
            asn[(kk + 0) * P1 + r0 + 64] = pa1.x * iA1; asn[(kk + 1) * P1 + r0 + 64] = pa1.y * iA1;
            asn[(kk + 2) * P1 + r0 + 64] = pa1.z * iA1; asn[(kk + 3) * P1 + r0 + 64] = pa1.w * iA1;
            bsn[(kk + 0) * P1 + r0] = pb0.x * iB0; bsn[(kk + 1) * P1 + r0] = pb0.y * iB0;
            bsn[(kk + 2) * P1 + r0] = pb0.z * iB0; bsn[(kk + 3) * P1 + r0] = pb0.w * iB0;
            bsn[(kk + 0) * P1 + r0 + 64] = pb1.x * iB1; bsn[(kk + 1) * P1 + r0 + 64] = pb1.y * iB1;
            bsn[(kk + 2) * P1 + r0 + 64] = pb1.z * iB1; bsn[(kk + 3) * P1 + r0 + 64] = pb1.w * iB1;
        }
        __syncthreads();
    }

    int lcols[4];
#pragma unroll
    for (int j = 0; j < 4; j++) lcols[j] = labels[(tx << 2) + j];

#pragma unroll
    for (int p = 0; p < 8; p++) {
        float s[4][2];
#pragma unroll
        for (int j = 0; j < 4; j++)
            asm("mov.b64 {%0, %1}, %2;" : "=f"(s[j][0]), "=f"(s[j][1]) : "l"(acc[p][j]));
#pragma unroll
        for (int h = 0; h < 2; h++) {
            int lrow = (ty << 4) + (p << 1) + h;
            int arow = rowStart + lrow;
            float d = dg[arow];
            float m = mg[arow];
            int la = labels[arow];
            unsigned long long best = ~0ull;
#pragma unroll
            for (int j = 0; j < 4; j++) {
                float loss = s[j][h] - d + m;
                if (loss > 0.f && loss < m && lcols[j] != la) {
                    int cb = (tx << 2) + j;
                    unsigned long long key = ((unsigned long long)cb << 32) |
                                             (unsigned long long)__float_as_uint(loss);
                    best = umin64(best, key);
                }
            }
            if (best != ~0ull) atomicMin(&sbest[lrow], best);
        }
    }
    __syncthreads();
    if (tid < BM) {
        unsigned long long v = sbest[tid];
        int arow = rowStart + tid;
        g_best[pass][arow] = v;
        bool okm = (*aflag == 0) || (mg[arow] >= 0.16f);
        if (okm && v == ~0ull) {
            int p = atomicAdd(&g_cnt[pass], 1);
            g_list[pass][p] = arow;
        }
    }
}

// -------- kernel 3: phase-2a gathered 64x64 GEMM + fused collect2 tail ------
__global__ __launch_bounds__(256) void phase2a_kernel(
    const float* __restrict__ img, const float* __restrict__ txt,
    const float* __restrict__ cr, const float* __restrict__ margin,
    const int* __restrict__ labels) {
    __shared__ __align__(16) float As[2][BK2 * P2A];
    __shared__ __align__(16) float Bs[2][BK2 * P2A];
    __shared__ int sList[64];
    __shared__ unsigned long long sbest[64];
    __shared__ int sLast;

    int pass = blockIdx.y;
    const float *A, *Bm, *iA, *iB, *dg, *mg;
    pass_ptrs(pass, margin, img, txt, cr, A, Bm, iA, iB, dg, mg);
    int cnt = g_cnt[pass];

    int colStart = W1 + blockIdx.x * 64;
    int tid = threadIdx.x;
    int tx = tid & 15, tyy = tid >> 4;
    int sr = tid & 63;
    int sk = (tid >> 6) << 3;

    float iB0 = iB[colStart + sr];
    const float* bRow = Bm + (size_t)(colStart + sr) * DD + sk;

    for (int base = 0; base < cnt; base += 64) {
        __syncthreads();
        if (tid < 64) {
            int idx = base + tid;
            sList[tid] = (idx < cnt) ? g_list[pass][idx] : g_list[pass][0];
            sbest[tid] = ~0ull;
        }
        __syncthreads();

        unsigned long long acc[4][2];
#pragma unroll
        for (int i = 0; i < 4; i++) { acc[i][0] = 0ull; acc[i][1] = 0ull; }

        int arowr = sList[sr];
        float iA0 = iA[arowr];
        const float* aPtr = A + (size_t)arowr * DD + sk;

        float4 va0 = *(const float4*)aPtr;
        float4 va1 = *(const float4*)(aPtr + 4);
        float4 vb0 = *(const float4*)bRow;
        float4 vb1 = *(const float4*)(bRow + 4);

        {
            float* as = As[0]; float* bs = Bs[0];
            as[(sk + 0) * P2A + sr] = va0.x * iA0; as[(sk + 1) * P2A + sr] = va0.y * iA0;
            as[(sk + 2) * P2A + sr] = va0.z * iA0; as[(sk + 3) * P2A + sr] = va0.w * iA0;
            as[(sk + 4) * P2A + sr] = va1.x * iA0; as[(sk + 5) * P2A + sr] = va1.y * iA0;
            as[(sk + 6) * P2A + sr] = va1.z * iA0; as[(sk + 7) * P2A + sr] = va1.w * iA0;
            bs[(sk + 0) * P2A + sr] = vb0.x * iB0; bs[(sk + 1) * P2A + sr] = vb0.y * iB0;
            bs[(sk + 2) * P2A + sr] = vb0.z * iB0; bs[(sk + 3) * P2A + sr] = vb0.w * iB0;
            bs[(sk + 4) * P2A + sr] = vb1.x * iB0; bs[(sk + 5) * P2A + sr] = vb1.y * iB0;
            bs[(sk + 6) * P2A + sr] = vb1.z * iB0; bs[(sk + 7) * P2A + sr] = vb1.w * iB0;
        }
        __syncthreads();

        for (int c = 0; c < NCH2; c++) {
            int cur = c & 1;
            bool more = (c + 1 < NCH2);
            if (more) {
                int kn = (c + 1) * BK2;
                va0 = *(const float4*)(aPtr + kn);
                va1 = *(const float4*)(aPtr + kn + 4);
                vb0 = *(const float4*)(bRow + kn);
                vb1 = *(const float4*)(bRow + kn + 4);
            }
            const float* as = As[cur];
            const float* bs = Bs[cur];
#pragma unroll
            for (int k = 0; k < BK2; k++) {
                float4 a0 = *(const float4*)&as[k * P2A + (tyy << 2)];
                ulonglong2 b0 = *(const ulonglong2*)&bs[k * P2A + (tx << 2)];
                float af[4] = {a0.x, a0.y, a0.z, a0.w};
#pragma unroll
                for (int i = 0; i < 4; i++) {
                    unsigned long long aa;
                    asm("mov.b64 %0, {%1, %1};" : "=l"(aa) : "f"(af[i]));
                    asm("fma.rn.f32x2 %0, %1, %2, %0;" : "+l"(acc[i][0]) : "l"(aa), "l"(b0.x));
                    asm("fma.rn.f32x2 %0, %1, %2, %0;" : "+l"(acc[i][1]) : "l"(aa), "l"(b0.y));
                }
            }
            if (more) {
                float* asn = As[cur ^ 1]; float* bsn = Bs[cur ^ 1];
                asn[(sk + 0) * P2A + sr] = va0.x * iA0; asn[(sk + 1) * P2A + sr] = va0.y * iA0;
                asn[(sk + 2) * P2A + sr] = va0.z * iA0; asn[(sk + 3) * P2A + sr] = va0.w * iA0;
                asn[(sk + 4) * P2A + sr] = va1.x * iA0; asn[(sk + 5) * P2A + sr] = va1.y * iA0;
                asn[(sk + 6) * P2A + sr] = va1.z * iA0; asn[(sk + 7) * P2A + sr] = va1.w * iA0;
                bsn[(sk + 0) * P2A + sr] = vb0.x * iB0; bsn[(sk + 1) * P2A + sr] = vb0.y * iB0;
                bsn[(sk + 2) * P2A + sr] = vb0.z * iB0; bsn[(sk + 3) * P2A + sr] = vb0.w * iB0;
                bsn[(sk + 4) * P2A + sr] = vb1.x * iB0; bsn[(sk + 5) * P2A + sr] = vb1.y * iB0;
                bsn[(sk + 6) * P2A + sr] = vb1.z * iB0; bsn[(sk + 7) * P2A + sr] = vb1.w * iB0;
            }
            __syncthreads();
        }

#pragma unroll
        for (int i = 0; i < 4; i++) {
            int lr = (tyy << 2) + i;
            if (base + lr >= cnt) continue;
            int arow = sList[lr];
            float d = dg[arow];
            float m = mg[arow];
            int la = labels[arow];
            unsigned long long best = ~0ull;
#pragma unroll
            for (int jp = 0; jp < 2; jp++) {
                float lo, hi;
                asm("mov.b64 {%0, %1}, %2;" : "=f"(lo), "=f"(hi) : "l"(acc[i][jp]));
                int cb = colStart + (tx << 2) + (jp << 1);
                float loss0 = lo - d + m;
                float loss1 = hi - d + m;
                if (loss0 > 0.f && loss0 < m && labels[cb] != la) {
                    unsigned long long key = ((unsigned long long)cb << 32) |
                                             (unsigned long long)__float_as_uint(loss0);
                    best = umin64(best, key);
                }
                if (loss1 > 0.f && loss1 < m && labels[cb + 1] != la) {
                    unsigned long long key = ((unsigned long long)(cb + 1) << 32) |
                                             (unsigned long long)__float_as_uint(loss1);
                    best = umin64(best, key);
                }
            }
            if (best != ~0ull) atomicMin(&sbest[lr], best);
        }
        __syncthreads();
        if (tid < 64 && base + tid < cnt && sbest[tid] != ~0ull)
            atomicMin(&g_best[pass][sList[tid]], sbest[tid]);
    }

    // fused collect2: last CTA of this pass scans the (small) stage-1 list
    __syncthreads();
    if (tid == 0) {
        __threadfence();
        sLast = (atomicAdd(&g_tick2a[pass], 1) == (int)gridDim.x - 1) ? 1 : 0;
    }
    __syncthreads();
    if (sLast) {
        __threadfence();
        for (int i = tid; i < cnt; i += 256) {
            int a = g_list[pass][i];
            if (__ldcg(&g_best[pass][a]) == ~0ull) {
                int p = atomicAdd(&g_cnt2[pass], 1);
                g_list2[pass][p] = a;
            }
        }
    }
}

// -------- kernel 4: phase-2b warp-streaming dots + fused final tail ---------
// unit = (anchor, 64-col chunk); warp-per-unit, grid-stride; no smem GEMM.
__global__ __launch_bounds__(256) void phase2b_kernel(
    const float* __restrict__ img, const float* __restrict__ txt,
    const float* __restrict__ cr, const float* __restrict__ margin,
    const int* __restrict__ labels, const int* __restrict__ aflag,
    const float* __restrict__ crbeta, float* __restrict__ out) {
    __shared__ int sLast;
    __shared__ double sh1[256], sh2[256];

    int pass = blockIdx.y;
    const float *A, *Bm, *iA, *iB, *dg, *mg;
    pass_ptrs(pass, margin, img, txt, cr, A, Bm, iA, iB, dg, mg);
    int cnt2 = g_cnt2[pass];
    int total = cnt2 * NCH2B;

    int tid = threadIdx.x;
    int wid = tid >> 5, lane = tid & 31;
    int gw = blockIdx.x * 8 + wid;
    int nwarps = gridDim.x * 8;

    for (int u = gw; u < total; u += nwarps) {
        int aidx = u / NCH2B;
        int ch = u - aidx * NCH2B;
        int a = g_list2[pass][aidx];
        float iA0 = iA[a];
        const float4* ap = (const float4*)(A + (size_t)a * DD);
        float4 av[4];
#pragma unroll
        for (int e = 0; e < 4; e++) {
            float4 v = ap[lane + 32 * e];
            av[e] = make_float4(v.x * iA0, v.y * iA0, v.z * iA0, v.w * iA0);
        }
        float d = dg[a], m = mg[a];
        int la = labels[a];
        int cbeg = W1 + W2 + ch * CH2B;
        unsigned long long best = ~0ull;

        for (int c = cbeg; c < cbeg + CH2B; c += 2) {
            const float4* b0 = (const float4*)(Bm + (size_t)c * DD);
            const float4* b1 = (const float4*)(Bm + (size_t)(c + 1) * DD);
            float s0 = 0.f, s1 = 0.f;
#pragma unroll
            for (int e = 0; e < 4; e++) {
                float4 v0 = b0[lane + 32 * e];
                float4 v1 = b1[lane + 32 * e];
                s0 += av[e].x * v0.x + av[e].y * v0.y + av[e].z * v0.z + av[e].w * v0.w;
                s1 += av[e].x * v1.x + av[e].y * v1.y + av[e].z * v1.z + av[e].w * v1.w;
            }
#pragma unroll
            for (int off = 16; off; off >>= 1) {
                s0 += __shfl_xor_sync(0xFFFFFFFFu, s0, off);
                s1 += __shfl_xor_sync(0xFFFFFFFFu, s1, off);
            }
            if (lane == 0) {
                float loss0 = s0 * iB[c] - d + m;
                float loss1 = s1 * iB[c + 1] - d + m;
                if (loss0 > 0.f && loss0 < m && labels[c] != la) {
                    unsigned long long key = ((unsigned long long)c << 32) |
                                             (unsigned long long)__float_as_uint(loss0);
                    best = umin64(best, key);
                }
                if (loss1 > 0.f && loss1 < m && labels[c + 1] != la) {
                    unsigned long long key = ((unsigned long long)(c + 1) << 32) |
                                             (unsigned long long)__float_as_uint(loss1);
                    best = umin64(best, key);
                }
            }
        }
        if (lane == 0 && best != ~0ull) atomicMin(&g_best[pass][a], best);
    }

    // fused final reduction: globally last CTA sums all mined losses
    __syncthreads();
    if (tid == 0) {
        __threadfence();
        int totalCtas = (int)(gridDim.x * gridDim.y);
        sLast = (atomicAdd(&g_tickb, 1) == totalCtas - 1) ? 1 : 0;
    }
    __syncthreads();
    if (sLast) {
        __threadfence();
        int af = *aflag;
        double s1 = 0.0, s2 = 0.0;
        for (int a = tid; a < BB; a += 256) {
            bool okb = af ? (margin[a] >= 0.16f) : true;
            bool okc = af ? (g_mcr[a] >= 0.16f) : true;
            unsigned long long v;
            v = __ldcg(&g_best[0][a]);
            if (okb && v != ~0ull) s1 += (double)__uint_as_float((unsigned)v);
            v = __ldcg(&g_best[1][a]);
            if (okb && v != ~0ull) s1 += (double)__uint_as_float((unsigned)v);
            v = __ldcg(&g_best[2][a]);
            if (okc && v != ~0ull) s2 += (double)__uint_as_float((unsigned)v);
            v = __ldcg(&g_best[3][a]);
            if (okc && v != ~0ull) s2 += (double)__uint_as_float((unsigned)v);
        }
        sh1[tid] = s1; sh2[tid] = s2;
        __syncthreads();
        for (int s = 128; s; s >>= 1) {
            if (tid < s) { sh1[tid] += sh1[tid + s]; sh2[tid] += sh2[tid + s]; }
            __syncthreads();
        }
        if (tid == 0) out[0] = (float)(sh1[0] + (double)crbeta[0] * sh2[0]);
    }
}

extern "C" void kernel_launch(void* const* d_in, const int* in_sizes, int n_in,
                              void* d_out, int out_size) {
    const float* img    = (const float*)d_in[0];
    const float* txt    = (const float*)d_in[1];
    const float* txtcr  = (const float*)d_in[2];
    const int*   labels = (const int*)d_in[3];
    const int*   aflag  = (const int*)d_in[4];
    const float* margin = (const float*)d_in[5];
    const float* crbeta = (const float*)d_in[6];
    float* out = (float*)d_out;

    prep_kernel<<<BB / 8, 256>>>(img, txt, txtcr, margin, aflag);
    phase1_kernel<<<dim3(BB / BM, 4), 256>>>(img, txt, txtcr, margin, labels, aflag);
    phase2a_kernel<<<dim3(W2 / 64, 4), 256>>>(img, txt, txtcr, margin, labels);
    phase2b_kernel<<<dim3(64, 4), 256>>>(img, txt, txtcr, margin, labels,
                                         aflag, crbeta, out);
}

// round 13
// speedup vs baseline: 1.1018x; 1.1018x over previous
#include <cuda_runtime.h>
#include <cuda_bf16.h>

#define BB 8192
#define DD 512
#define W1 128          // phase-1 candidate window
#define W2 2048         // phase-2a candidate window
#define BM 128
#define BK 16
#define NCH (DD / BK)   // 32 k-chunks
#define BK2 32
#define NCH2 (DD / BK2) // 16 k-chunks (phase2a)
#define P1 132          // phase1 padded smem row
#define P2A 68          // phase2 pad (64 + 4)
#define MAXA 8          // phase2b anchors per smem chunk

// -------- scratch (device globals; no allocation allowed) --------
__device__ float g_inva[BB];
__device__ float g_invt[BB];
__device__ float g_invc[BB];
__device__ float g_sm[BB];
__device__ float g_smcr[BB];
__device__ float g_mcr[BB];
__device__ unsigned long long g_best[4][BB];
__device__ int g_cnt[4];
__device__ int g_list[4][BB];
__device__ int g_cnt2[4];
__device__ int g_list2[4][BB];
__device__ int g_tick2a[4];
__device__ int g_tickb;

static __device__ __forceinline__ unsigned long long umin64(unsigned long long a,
                                                            unsigned long long b) {
    return a < b ? a : b;
}

static __device__ __forceinline__ void pass_ptrs(
    int pass, const float* margin, const float* img, const float* txt, const float* cr,
    const float*& A, const float*& Bm, const float*& iA, const float*& iB,
    const float*& dg, const float*& mg) {
    switch (pass) {
        case 0: A = img; Bm = txt; iA = g_inva; iB = g_invt; dg = g_sm;   mg = margin; break;
        case 1: A = txt; Bm = img; iA = g_invt; iB = g_inva; dg = g_sm;   mg = margin; break;
        case 2: A = img; Bm = cr;  iA = g_inva; iB = g_invc; dg = g_smcr; mg = g_mcr;  break;
        default:A = cr;  Bm = img; iA = g_invc; iB = g_inva; dg = g_smcr; mg = g_mcr;  break;
    }
}

// -------- kernel 1: norms, diag sims, margin_cr, state reset ----------------
__global__ __launch_bounds__(256) void prep_kernel(
    const float* __restrict__ img, const float* __restrict__ txt,
    const float* __restrict__ cr, const float* __restrict__ margin,
    const int* __restrict__ aflag) {
    int row = blockIdx.x * 8 + (threadIdx.x >> 5);
    int lane = threadIdx.x & 31;
    const float4* pi = (const float4*)(img + (size_t)row * DD);
    const float4* pt = (const float4*)(txt + (size_t)row * DD);
    const float4* pc = (const float4*)(cr + (size_t)row * DD);

    float sii = 0.f, stt = 0.f, scc = 0.f, sit = 0.f, sic = 0.f;
#pragma unroll
    for (int e = 0; e < 4; e++) {
        float4 vi = pi[lane + 32 * e];
        float4 vt = pt[lane + 32 * e];
        float4 vc = pc[lane + 32 * e];
        sii += vi.x * vi.x + vi.y * vi.y + vi.z * vi.z + vi.w * vi.w;
        stt += vt.x * vt.x + vt.y * vt.y + vt.z * vt.z + vt.w * vt.w;
        scc += vc.x * vc.x + vc.y * vc.y + vc.z * vc.z + vc.w * vc.w;
        sit += vi.x * vt.x + vi.y * vt.y + vi.z * vt.z + vi.w * vt.w;
        sic += vi.x * vc.x + vi.y * vc.y + vi.z * vc.z + vi.w * vc.w;
    }
#pragma unroll
    for (int off = 16; off; off >>= 1) {
        sii += __shfl_xor_sync(0xFFFFFFFFu, sii, off);
        stt += __shfl_xor_sync(0xFFFFFFFFu, stt, off);
        scc += __shfl_xor_sync(0xFFFFFFFFu, scc, off);
        sit += __shfl_xor_sync(0xFFFFFFFFu, sit, off);
        sic += __shfl_xor_sync(0xFFFFFFFFu, sic, off);
    }
    if (lane == 0) {
        float inva = 1.f / (sqrtf(sii) + 1e-8f);
        float invt = 1.f / (sqrtf(stt) + 1e-8f);
        float invc = 1.f / (sqrtf(scc) + 1e-8f);
        g_inva[row] = inva; g_invt[row] = invt; g_invc[row] = invc;
        float sm = sit * inva * invt;
        float smcr = sic * inva * invc;
        g_sm[row] = sm;
        g_smcr[row] = smcr;
        float mrg = margin[row];
        float mcr;
        if (*aflag) {
            float lam = fminf(fabsf(smcr) / fabsf(sm), 1.f);
            mcr = (lam + 1.f) * mrg * 0.5f;
        } else {
            mcr = mrg * 0.5f;
        }
        g_mcr[row] = mcr;
    }
    if (blockIdx.x == 0 && threadIdx.x < 4) {
        g_cnt[threadIdx.x] = 0;
        g_cnt2[threadIdx.x] = 0;
        g_tick2a[threadIdx.x] = 0;
        if (threadIdx.x == 0) g_tickb = 0;
    }
}

// -------- kernel 2: phase-1 128x128 strip GEMM (16x4 microtile) + collect ---
__global__ __launch_bounds__(256, 2) void phase1_kernel(
    const float* __restrict__ img, const float* __restrict__ txt,
    const float* __restrict__ cr, const float* __restrict__ margin,
    const int* __restrict__ labels, const int* __restrict__ aflag) {
    __shared__ __align__(16) float As[2][BK * P1];
    __shared__ __align__(16) float Bs[2][BK * P1];
    __shared__ unsigned long long sbest[BM];

    int pass = blockIdx.y;
    const float *A, *Bm, *iA, *iB, *dg, *mg;
    pass_ptrs(pass, margin, img, txt, cr, A, Bm, iA, iB, dg, mg);

    int rowStart = blockIdx.x * BM;
    int tid = threadIdx.x;
    int tx = tid & 31;        // col group: 4 cols at 4*tx
    int ty = tid >> 5;        // row group: 16 rows at 16*ty

    if (tid < BM) sbest[tid] = ~0ull;

    unsigned long long acc[8][4];
#pragma unroll
    for (int i = 0; i < 8; i++)
#pragma unroll
        for (int j = 0; j < 4; j++) acc[i][j] = 0ull;

    int r0 = tid >> 2;
    int kk = (tid & 3) << 2;

    float iA0 = iA[rowStart + r0];
    float iA1 = iA[rowStart + r0 + 64];
    float iB0 = iB[r0];
    float iB1 = iB[r0 + 64];
    const float* aRow0 = A + (size_t)(rowStart + r0) * DD + kk;
    const float* aRow1 = A + (size_t)(rowStart + r0 + 64) * DD + kk;
    const float* bRow0 = Bm + (size_t)r0 * DD + kk;
    const float* bRow1 = Bm + (size_t)(r0 + 64) * DD + kk;

    float4 pa0 = *(const float4*)aRow0;
    float4 pa1 = *(const float4*)aRow1;
    float4 pb0 = *(const float4*)bRow0;
    float4 pb1 = *(const float4*)bRow1;

    {
        float* as = As[0]; float* bs = Bs[0];
        as[(kk + 0) * P1 + r0] = pa0.x * iA0; as[(kk + 1) * P1 + r0] = pa0.y * iA0;
        as[(kk + 2) * P1 + r0] = pa0.z * iA0; as[(kk + 3) * P1 + r0] = pa0.w * iA0;
        as[(kk + 0) * P1 + r0 + 64] = pa1.x * iA1; as[(kk + 1) * P1 + r0 + 64] = pa1.y * iA1;
        as[(kk + 2) * P1 + r0 + 64] = pa1.z * iA1; as[(kk + 3) * P1 + r0 + 64] = pa1.w * iA1;
        bs[(kk + 0) * P1 + r0] = pb0.x * iB0; bs[(kk + 1) * P1 + r0] = pb0.y * iB0;
        bs[(kk + 2) * P1 + r0] = pb0.z * iB0; bs[(kk + 3) * P1 + r0] = pb0.w * iB0;
        bs[(kk + 0) * P1 + r0 + 64] = pb1.x * iB1; bs[(kk + 1) * P1 + r0 + 64] = pb1.y * iB1;
        bs[(kk + 2) * P1 + r0 + 64] = pb1.z * iB1; bs[(kk + 3) * P1 + r0 + 64] = pb1.w * iB1;
    }
    __syncthreads();

    for (int c = 0; c < NCH; c++) {
        int cur = c & 1;
        bool more = (c + 1 < NCH);
        if (more) {
            int kn = (c + 1) * BK;
            pa0 = *(const float4*)(aRow0 + kn);
            pa1 = *(const float4*)(aRow1 + kn);
            pb0 = *(const float4*)(bRow0 + kn);
            pb1 = *(const float4*)(bRow1 + kn);
        }
        const float* as = As[cur];
        const float* bs = Bs[cur];
#pragma unroll
        for (int k = 0; k < BK; k++) {
            ulonglong2 q0 = *(const ulonglong2*)&as[k * P1 + (ty << 4)];
            ulonglong2 q1 = *(const ulonglong2*)&as[k * P1 + (ty << 4) + 4];
            ulonglong2 q2 = *(const ulonglong2*)&as[k * P1 + (ty << 4) + 8];
            ulonglong2 q3 = *(const ulonglong2*)&as[k * P1 + (ty << 4) + 12];
            float4 bv = *(const float4*)&bs[k * P1 + (tx << 2)];
            unsigned long long bd0, bd1, bd2, bd3;
            asm("mov.b64 %0, {%1, %1};" : "=l"(bd0) : "f"(bv.x));
            asm("mov.b64 %0, {%1, %1};" : "=l"(bd1) : "f"(bv.y));
            asm("mov.b64 %0, {%1, %1};" : "=l"(bd2) : "f"(bv.z));
            asm("mov.b64 %0, {%1, %1};" : "=l"(bd3) : "f"(bv.w));
            unsigned long long ap[8] = {q0.x, q0.y, q1.x, q1.y, q2.x, q2.y, q3.x, q3.y};
#pragma unroll
            for (int p = 0; p < 8; p++) {
                asm("fma.rn.f32x2 %0, %1, %2, %0;" : "+l"(acc[p][0]) : "l"(ap[p]), "l"(bd0));
                asm("fma.rn.f32x2 %0, %1, %2, %0;" : "+l"(acc[p][1]) : "l"(ap[p]), "l"(bd1));
                asm("fma.rn.f32x2 %0, %1, %2, %0;" : "+l"(acc[p][2]) : "l"(ap[p]), "l"(bd2));
                asm("fma.rn.f32x2 %0, %1, %2, %0;" : "+l"(acc[p][3]) : "l"(ap[p]), "l"(bd3));
            }
        }
        if (more) {
            float* asn = As[cur ^ 1]; float* bsn = Bs[cur ^ 1];
            asn[(kk + 0) * P1 + r0] = pa0.x * iA0; asn[(kk + 1) * P1 + r0] = pa0.y * iA0;
            asn[(kk + 2) * P1 + r0] = pa0.z * iA0; asn[(kk + 3) * P1 + r0] = pa0.w * iA0;
            asn[(kk + 0) * P1 + r0 + 64] = pa1.x * iA1; asn[(kk + 1) * P1 + r0 + 64] = pa1.y * iA1;
            asn[(kk + 2) * P1 + r0 + 64] = pa1.z * iA1; asn[(kk + 3) * P1 + r0 + 64] = pa1.w * iA1;
            bsn[(kk + 0) * P1 + r0] = pb0.x * iB0; bsn[(kk + 1) * P1 + r0] = pb0.y * iB0;
            bsn[(kk + 2) * P1 + r0] = pb0.z * iB0; bsn[(kk + 3) * P1 + r0] = pb0.w * iB0;
            bsn[(kk + 0) * P1 + r0 + 64] = pb1.x * iB1; bsn[(kk + 1) * P1 + r0 + 64] = pb1.y * iB1;
            bsn[(kk + 2) * P1 + r0 + 64] = pb1.z * iB1; bsn[(kk + 3) * P1 + r0 + 64] = pb1.w * iB1;
        }
        __syncthreads();
    }

    int lcols[4];
#pragma unroll
    for (int j = 0; j < 4; j++) lcols[j] = labels[(tx << 2) + j];

#pragma unroll
    for (int p = 0; p < 8; p++) {
        float s[4][2];
#pragma unroll
        for (int j = 0; j < 4; j++)
            asm("mov.b64 {%0, %1}, %2;" : "=f"(s[j][0]), "=f"(s[j][1]) : "l"(acc[p][j]));
#pragma unroll
        for (int h = 0; h < 2; h++) {
            int lrow = (ty << 4) + (p << 1) + h;
            int arow = rowStart + lrow;
            float d = dg[arow];
            float m = mg[arow];
            int la = labels[arow];
            unsigned long long best = ~0ull;
#pragma unroll
            for (int j = 0; j < 4; j++) {
                float loss = s[j][h] - d + m;
                if (loss > 0.f && loss < m && lcols[j] != la) {
                    int cb = (tx << 2) + j;
                    unsigned long long key = ((unsigned long long)cb << 32) |
                                             (unsigned long long)__float_as_uint(loss);
                    best = umin64(best, key);
                }
            }
            if (best != ~0ull) atomicMin(&sbest[lrow], best);
        }
    }
    __syncthreads();
    if (tid < BM) {
        unsigned long long v = sbest[tid];
        int arow = rowStart + tid;
        g_best[pass][arow] = v;
        bool okm = (*aflag == 0) || (mg[arow] >= 0.16f);
        if (okm && v == ~0ull) {
            int p = atomicAdd(&g_cnt[pass], 1);
            g_list[pass][p] = arow;
        }
    }
}

// -------- kernel 3: phase-2a gathered 64x64 GEMM + fused collect2 tail ------
__global__ __launch_bounds__(256) void phase2a_kernel(
    const float* __restrict__ img, const float* __restrict__ txt,
    const float* __restrict__ cr, const float* __restrict__ margin,
    const int* __restrict__ labels) {
    __shared__ __align__(16) float As[2][BK2 * P2A];
    __shared__ __align__(16) float Bs[2][BK2 * P2A];
    __shared__ int sList[64];
    __shared__ unsigned long long sbest[64];
    __shared__ int sLast;

    int pass = blockIdx.y;
    const float *A, *Bm, *iA, *iB, *dg, *mg;
    pass_ptrs(pass, margin, img, txt, cr, A, Bm, iA, iB, dg, mg);
    int cnt = g_cnt[pass];

    int colStart = W1 + blockIdx.x * 64;
    int tid = threadIdx.x;
    int tx = tid & 15, tyy = tid >> 4;
    int sr = tid & 63;
    int sk = (tid >> 6) << 3;

    float iB0 = iB[colStart + sr];
    const float* bRow = Bm + (size_t)(colStart + sr) * DD + sk;

    for (int base = 0; base < cnt; base += 64) {
        __syncthreads();
        if (tid < 64) {
            int idx = base + tid;
            sList[tid] = (idx < cnt) ? g_list[pass][idx] : g_list[pass][0];
            sbest[tid] = ~0ull;
        }
        __syncthreads();

        unsigned long long acc[4][2];
#pragma unroll
        for (int i = 0; i < 4; i++) { acc[i][0] = 0ull; acc[i][1] = 0ull; }

        int arowr = sList[sr];
        float iA0 = iA[arowr];
        const float* aPtr = A + (size_t)arowr * DD + sk;

        float4 va0 = *(const float4*)aPtr;
        float4 va1 = *(const float4*)(aPtr + 4);
        float4 vb0 = *(const float4*)bRow;
        float4 vb1 = *(const float4*)(bRow + 4);

        {
            float* as = As[0]; float* bs = Bs[0];
            as[(sk + 0) * P2A + sr] = va0.x * iA0; as[(sk + 1) * P2A + sr] = va0.y * iA0;
            as[(sk + 2) * P2A + sr] = va0.z * iA0; as[(sk + 3) * P2A + sr] = va0.w * iA0;
            as[(sk + 4) * P2A + sr] = va1.x * iA0; as[(sk + 5) * P2A + sr] = va1.y * iA0;
            as[(sk + 6) * P2A + sr] = va1.z * iA0; as[(sk + 7) * P2A + sr] = va1.w * iA0;
            bs[(sk + 0) * P2A + sr] = vb0.x * iB0; bs[(sk + 1) * P2A + sr] = vb0.y * iB0;
            bs[(sk + 2) * P2A + sr] = vb0.z * iB0; bs[(sk + 3) * P2A + sr] = vb0.w * iB0;
            bs[(sk + 4) * P2A + sr] = vb1.x * iB0; bs[(sk + 5) * P2A + sr] = vb1.y * iB0;
            bs[(sk + 6) * P2A + sr] = vb1.z * iB0; bs[(sk + 7) * P2A + sr] = vb1.w * iB0;
        }
        __syncthreads();

        for (int c = 0; c < NCH2; c++) {
            int cur = c & 1;
            bool more = (c + 1 < NCH2);
            if (more) {
                int kn = (c + 1) * BK2;
                va0 = *(const float4*)(aPtr + kn);
                va1 = *(const float4*)(aPtr + kn + 4);
                vb0 = *(const float4*)(bRow + kn);
                vb1 = *(const float4*)(bRow + kn + 4);
            }
            const float* as = As[cur];
            const float* bs = Bs[cur];
#pragma unroll
            for (int k = 0; k < BK2; k++) {
                float4 a0 = *(const float4*)&as[k * P2A + (tyy << 2)];
                ulonglong2 b0 = *(const ulonglong2*)&bs[k * P2A + (tx << 2)];
                float af[4] = {a0.x, a0.y, a0.z, a0.w};
#pragma unroll
                for (int i = 0; i < 4; i++) {
                    unsigned long long aa;
                    asm("mov.b64 %0, {%1, %1};" : "=l"(aa) : "f"(af[i]));
                    asm("fma.rn.f32x2 %0, %1, %2, %0;" : "+l"(acc[i][0]) : "l"(aa), "l"(b0.x));
                    asm("fma.rn.f32x2 %0, %1, %2, %0;" : "+l"(acc[i][1]) : "l"(aa), "l"(b0.y));
                }
            }
            if (more) {
                float* asn = As[cur ^ 1]; float* bsn = Bs[cur ^ 1];
                asn[(sk + 0) * P2A + sr] = va0.x * iA0; asn[(sk + 1) * P2A + sr] = va0.y * iA0;
                asn[(sk + 2) * P2A + sr] = va0.z * iA0; asn[(sk + 3) * P2A + sr] = va0.w * iA0;
                asn[(sk + 4) * P2A + sr] = va1.x * iA0; asn[(sk + 5) * P2A + sr] = va1.y * iA0;
                asn[(sk + 6) * P2A + sr] = va1.z * iA0; asn[(sk + 7) * P2A + sr] = va1.w * iA0;
                bsn[(sk + 0) * P2A + sr] = vb0.x * iB0; bsn[(sk + 1) * P2A + sr] = vb0.y * iB0;
                bsn[(sk + 2) * P2A + sr] = vb0.z * iB0; bsn[(sk + 3) * P2A + sr] = vb0.w * iB0;
                bsn[(sk + 4) * P2A + sr] = vb1.x * iB0; bsn[(sk + 5) * P2A + sr] = vb1.y * iB0;
                bsn[(sk + 6) * P2A + sr] = vb1.z * iB0; bsn[(sk + 7) * P2A + sr] = vb1.w * iB0;
            }
            __syncthreads();
        }

#pragma unroll
        for (int i = 0; i < 4; i++) {
            int lr = (tyy << 2) + i;
            if (base + lr >= cnt) continue;
            int arow = sList[lr];
            float d = dg[arow];
            float m = mg[arow];
            int la = labels[arow];
            unsigned long long best = ~0ull;
#pragma unroll
            for (int jp = 0; jp < 2; jp++) {
                float lo, hi;
                asm("mov.b64 {%0, %1}, %2;" : "=f"(lo), "=f"(hi) : "l"(acc[i][jp]));
                int cb = colStart + (tx << 2) + (jp << 1);
                float loss0 = lo - d + m;
                float loss1 = hi - d + m;
                if (loss0 > 0.f && loss0 < m && labels[cb] != la) {
                    unsigned long long key = ((unsigned long long)cb << 32) |
                                             (unsigned long long)__float_as_uint(loss0);
                    best = umin64(best, key);
                }
                if (loss1 > 0.f && loss1 < m && labels[cb + 1] != la) {
                    unsigned long long key = ((unsigned long long)(cb + 1) << 32) |
                                             (unsigned long long)__float_as_uint(loss1);
                    best = umin64(best, key);
                }
            }
            if (best != ~0ull) atomicMin(&sbest[lr], best);
        }
        __syncthreads();
        if (tid < 64 && base + tid < cnt && sbest[tid] != ~0ull)
            atomicMin(&g_best[pass][sList[tid]], sbest[tid]);
    }

    // fused collect2: last CTA of this pass scans the (small) stage-1 list
    __syncthreads();
    if (tid == 0) {
        __threadfence();
        sLast = (atomicAdd(&g_tick2a[pass], 1) == (int)gridDim.x - 1) ? 1 : 0;
    }
    __syncthreads();
    if (sLast) {
        __threadfence();
        for (int i = tid; i < cnt; i += 256) {
            int a = g_list[pass][i];
            if (__ldcg(&g_best[pass][a]) == ~0ull) {
                int p = atomicAdd(&g_cnt2[pass], 1);
                g_list2[pass][p] = a;
            }
        }
    }
}

// -------- kernel 4: phase-2b thread-per-column scan + fused final tail ------
// Each thread owns one column; anchors (<=MAXA at a time) broadcast from smem.
__global__ __launch_bounds__(256) void phase2b_kernel(
    const float* __restrict__ img, const float* __restrict__ txt,
    const float* __restrict__ cr, const float* __restrict__ margin,
    const int* __restrict__ labels, const int* __restrict__ aflag,
    const float* __restrict__ crbeta, float* __restrict__ out) {
    __shared__ __align__(16) float sA[MAXA][DD];   // 16 KB pre-scaled anchor rows
    __shared__ float sd[MAXA], smg[MAXA];
    __shared__ int sLab[MAXA], sIdx[MAXA];
    __shared__ int sLast;
    __shared__ double sh1[256], sh2[256];

    int pass = blockIdx.y;
    const float *A, *Bm, *iA, *iB, *dg, *mg;
    pass_ptrs(pass, margin, img, txt, cr, A, Bm, iA, iB, dg, mg);
    int cnt2 = g_cnt2[pass];

    int tid = threadIdx.x;
    int col = W1 + W2 + blockIdx.x * 256 + tid;
    bool colok = (col < BB);
    int cSafe = colok ? col : (BB - 1);
    float iBc = iB[cSafe];
    int lc = labels[cSafe];
    const float4* brow = (const float4*)(Bm + (size_t)cSafe * DD);

    for (int base = 0; base < cnt2; base += MAXA) {
        __syncthreads();   // guard smem reuse
        // stage anchors (pad with duplicates of entry `base` — idempotent)
        for (int q = tid; q < MAXA * (DD / 4); q += 256) {
            int anc = q >> 7;              // q / 128
            int e = q & 127;
            int idx = base + anc;
            int a = g_list2[pass][idx < cnt2 ? idx : base];
            float iA0 = iA[a];
            float4 v = ((const float4*)(A + (size_t)a * DD))[e];
            ((float4*)sA[anc])[e] = make_float4(v.x * iA0, v.y * iA0, v.z * iA0, v.w * iA0);
        }
        if (tid < MAXA) {
            int idx = base + tid;
            int a = g_list2[pass][idx < cnt2 ? idx : base];
            sIdx[tid] = a;
            sd[tid] = dg[a];
            smg[tid] = mg[a];
            sLab[tid] = labels[a];
        }
        __syncthreads();

        if (colok) {
            float acc[MAXA];
#pragma unroll
            for (int i = 0; i < MAXA; i++) acc[i] = 0.f;
#pragma unroll 4
            for (int e = 0; e < DD / 4; e++) {
                float4 b = brow[e];
#pragma unroll
                for (int anc = 0; anc < MAXA; anc++) {
                    float4 av = ((const float4*)sA[anc])[e];
                    acc[anc] += b.x * av.x + b.y * av.y + b.z * av.z + b.w * av.w;
                }
            }
#pragma unroll
            for (int anc = 0; anc < MAXA; anc++) {
                float m = smg[anc];
                float loss = acc[anc] * iBc - sd[anc] + m;
                if (loss > 0.f && loss < m && lc != sLab[anc]) {
                    unsigned long long key = ((unsigned long long)col << 32) |
                                             (unsigned long long)__float_as_uint(loss);
                    atomicMin(&g_best[pass][sIdx[anc]], key);
                }
            }
        }
    }

    // fused final reduction: globally last CTA sums all mined losses
    __syncthreads();
    if (tid == 0) {
        __threadfence();
        int totalCtas = (int)(gridDim.x * gridDim.y);
        sLast = (atomicAdd(&g_tickb, 1) == totalCtas - 1) ? 1 : 0;
    }
    __syncthreads();
    if (sLast) {
        __threadfence();
        int af = *aflag;
        double s1 = 0.0, s2 = 0.0;
        for (int a = tid; a < BB; a += 256) {
            bool okb = af ? (margin[a] >= 0.16f) : true;
            bool okc = af ? (g_mcr[a] >= 0.16f) : true;
            unsigned long long v;
            v = __ldcg(&g_best[0][a]);
            if (okb && v != ~0ull) s1 += (double)__uint_as_float((unsigned)v);
            v = __ldcg(&g_best[1][a]);
            if (okb && v != ~0ull) s1 += (double)__uint_as_float((unsigned)v);
            v = __ldcg(&g_best[2][a]);
            if (okc && v != ~0ull) s2 += (double)__uint_as_float((unsigned)v);
            v = __ldcg(&g_best[3][a]);
            if (okc && v != ~0ull) s2 += (double)__uint_as_float((unsigned)v);
        }
        sh1[tid] = s1; sh2[tid] = s2;
        __syncthreads();
        for (int s = 128; s; s >>= 1) {
            if (tid < s) { sh1[tid] += sh1[tid + s]; sh2[tid] += sh2[tid + s]; }
            __syncthreads();
        }
        if (tid == 0) out[0] = (float)(sh1[0] + (double)crbeta[0] * sh2[0]);
    }
}

extern "C" void kernel_launch(void* const* d_in, const int* in_sizes, int n_in,
                              void* d_out, int out_size) {
    const float* img    = (const float*)d_in[0];
    const float* txt    = (const float*)d_in[1];
    const float* txtcr  = (const float*)d_in[2];
    const int*   labels = (const int*)d_in[3];
    const int*   aflag  = (const int*)d_in[4];
    const float* margin = (const float*)d_in[5];
    const float* crbeta = (const float*)d_in[6];
    float* out = (float*)d_out;

    prep_kernel<<<BB / 8, 256>>>(img, txt, txtcr, margin, aflag);
    phase1_kernel<<<dim3(BB / BM, 4), 256>>>(img, txt, txtcr, margin, labels, aflag);
    phase2a_kernel<<<dim3(W2 / 64, 4), 256>>>(img, txt, txtcr, margin, labels);
    phase2b_kernel<<<dim3((BB - W1 - W2 + 255) / 256, 4), 256>>>(img, txt, txtcr, margin,
                                                                 labels, aflag, crbeta, out);
}

// round 14
// speedup vs baseline: 1.1369x; 1.0318x over previous
#include <cuda_runtime.h>
#include <cuda_bf16.h>

#define BB 8192
#define DD 512
#define W1 128          // phase-1 candidate window
#define W2 2048         // phase-2a candidate window
#define BM 128
#define BK 16
#define NCH (DD / BK)   // 32 k-chunks
#define BK2 32
#define NCH2 (DD / BK2) // 16 k-chunks (phase2a)
#define P1 132          // phase1 padded smem row
#define P2A 68          // phase2 pad (64 + 4)
#define MAXA 8          // phase2b anchors per smem chunk

// -------- scratch (device globals; no allocation allowed) --------
__device__ float g_inva[BB];
__device__ float g_invt[BB];
__device__ float g_invc[BB];
__device__ float g_sm[BB];
__device__ float g_smcr[BB];
__device__ float g_mcr[BB];
__device__ unsigned long long g_best[4][BB];
__device__ int g_cnt[4];
__device__ int g_list[4][BB];
__device__ int g_cnt2[4];
__device__ int g_list2[4][BB];
__device__ int g_tick2a[4];
__device__ int g_tickb;

static __device__ __forceinline__ unsigned long long umin64(unsigned long long a,
                                                            unsigned long long b) {
    return a < b ? a : b;
}

static __device__ __forceinline__ void pass_ptrs(
    int pass, const float* margin, const float* img, const float* txt, const float* cr,
    const float*& A, const float*& Bm, const float*& iA, const float*& iB,
    const float*& dg, const float*& mg) {
    switch (pass) {
        case 0: A = img; Bm = txt; iA = g_inva; iB = g_invt; dg = g_sm;   mg = margin; break;
        case 1: A = txt; Bm = img; iA = g_invt; iB = g_inva; dg = g_sm;   mg = margin; break;
        case 2: A = img; Bm = cr;  iA = g_inva; iB = g_invc; dg = g_smcr; mg = g_mcr;  break;
        default:A = cr;  Bm = img; iA = g_invc; iB = g_inva; dg = g_smcr; mg = g_mcr;  break;
    }
}

// -------- kernel 1: norms, diag sims, margin_cr, state reset ----------------
__global__ __launch_bounds__(256) void prep_kernel(
    const float* __restrict__ img, const float* __restrict__ txt,
    const float* __restrict__ cr, const float* __restrict__ margin,
    const int* __restrict__ aflag) {
    int row = blockIdx.x * 8 + (threadIdx.x >> 5);
    int lane = threadIdx.x & 31;
    const float4* pi = (const float4*)(img + (size_t)row * DD);
    const float4* pt = (const float4*)(txt + (size_t)row * DD);
    const float4* pc = (const float4*)(cr + (size_t)row * DD);

    float sii = 0.f, stt = 0.f, scc = 0.f, sit = 0.f, sic = 0.f;
#pragma unroll
    for (int e = 0; e < 4; e++) {
        float4 vi = pi[lane + 32 * e];
        float4 vt = pt[lane + 32 * e];
        float4 vc = pc[lane + 32 * e];
        sii += vi.x * vi.x + vi.y * vi.y + vi.z * vi.z + vi.w * vi.w;
        stt += vt.x * vt.x + vt.y * vt.y + vt.z * vt.z + vt.w * vt.w;
        scc += vc.x * vc.x + vc.y * vc.y + vc.z * vc.z + vc.w * vc.w;
        sit += vi.x * vt.x + vi.y * vt.y + vi.z * vt.z + vi.w * vt.w;
        sic += vi.x * vc.x + vi.y * vc.y + vi.z * vc.z + vi.w * vc.w;
    }
#pragma unroll
    for (int off = 16; off; off >>= 1) {
        sii += __shfl_xor_sync(0xFFFFFFFFu, sii, off);
        stt += __shfl_xor_sync(0xFFFFFFFFu, stt, off);
        scc += __shfl_xor_sync(0xFFFFFFFFu, scc, off);
        sit += __shfl_xor_sync(0xFFFFFFFFu, sit, off);
        sic += __shfl_xor_sync(0xFFFFFFFFu, sic, off);
    }
    if (lane == 0) {
        float inva = 1.f / (sqrtf(sii) + 1e-8f);
        float invt = 1.f / (sqrtf(stt) + 1e-8f);
        float invc = 1.f / (sqrtf(scc) + 1e-8f);
        g_inva[row] = inva; g_invt[row] = invt; g_invc[row] = invc;
        float sm = sit * inva * invt;
        float smcr = sic * inva * invc;
        g_sm[row] = sm;
        g_smcr[row] = smcr;
        float mrg = margin[row];
        float mcr;
        if (*aflag) {
            float lam = fminf(fabsf(smcr) / fabsf(sm), 1.f);
            mcr = (lam + 1.f) * mrg * 0.5f;
        } else {
            mcr = mrg * 0.5f;
        }
        g_mcr[row] = mcr;
    }
    if (blockIdx.x == 0 && threadIdx.x < 4) {
        g_cnt[threadIdx.x] = 0;
        g_cnt2[threadIdx.x] = 0;
        g_tick2a[threadIdx.x] = 0;
        if (threadIdx.x == 0) g_tickb = 0;
    }
}

// -------- kernel 2: phase-1 128x128 strip GEMM (16x4 microtile) + collect ---
__global__ __launch_bounds__(256, 2) void phase1_kernel(
    const float* __restrict__ img, const float* __restrict__ txt,
    const float* __restrict__ cr, const float* __restrict__ margin,
    const int* __restrict__ labels, const int* __restrict__ aflag) {
    __shared__ __align__(16) float As[2][BK * P1];
    __shared__ __align__(16) float Bs[2][BK * P1];
    __shared__ unsigned long long sbest[BM];

    int pass = blockIdx.y;
    const float *A, *Bm, *iA, *iB, *dg, *mg;
    pass_ptrs(pass, margin, img, txt, cr, A, Bm, iA, iB, dg, mg);

    int rowStart = blockIdx.x * BM;
    int tid = threadIdx.x;
    int tx = tid & 31;
    int ty = tid >> 5;

    if (tid < BM) sbest[tid] = ~0ull;

    unsigned long long acc[8][4];
#pragma unroll
    for (int i = 0; i < 8; i++)
#pragma unroll
        for (int j = 0; j < 4; j++) acc[i][j] = 0ull;

    int r0 = tid >> 2;
    int kk = (tid & 3) << 2;

    float iA0 = iA[rowStart + r0];
    float iA1 = iA[rowStart + r0 + 64];
    float iB0 = iB[r0];
    float iB1 = iB[r0 + 64];
    const float* aRow0 = A + (size_t)(rowStart + r0) * DD + kk;
    const float* aRow1 = A + (size_t)(rowStart + r0 + 64) * DD + kk;
    const float* bRow0 = Bm + (size_t)r0 * DD + kk;
    const float* bRow1 = Bm + (size_t)(r0 + 64) * DD + kk;

    float4 pa0 = *(const float4*)aRow0;
    float4 pa1 = *(const float4*)aRow1;
    float4 pb0 = *(const float4*)bRow0;
    float4 pb1 = *(const float4*)bRow1;

    {
        float* as = As[0]; float* bs = Bs[0];
        as[(kk + 0) * P1 + r0] = pa0.x * iA0; as[(kk + 1) * P1 + r0] = pa0.y * iA0;
        as[(kk + 2) * P1 + r0] = pa0.z * iA0; as[(kk + 3) * P1 + r0] = pa0.w * iA0;
        as[(kk + 0) * P1 + r0 + 64] = pa1.x * iA1; as[(kk + 1) * P1 + r0 + 64] = pa1.y * iA1;
        as[(kk + 2) * P1 + r0 + 64] = pa1.z * iA1; as[(kk + 3) * P1 + r0 + 64] = pa1.w * iA1;
        bs[(kk + 0) * P1 + r0] = pb0.x * iB0; bs[(kk + 1) * P1 + r0] = pb0.y * iB0;
        bs[(kk + 2) * P1 + r0] = pb0.z * iB0; bs[(kk + 3) * P1 + r0] = pb0.w * iB0;
        bs[(kk + 0) * P1 + r0 + 64] = pb1.x * iB1; bs[(kk + 1) * P1 + r0 + 64] = pb1.y * iB1;
        bs[(kk + 2) * P1 + r0 + 64] = pb1.z * iB1; bs[(kk + 3) * P1 + r0 + 64] = pb1.w * iB1;
    }
    __syncthreads();

    for (int c = 0; c < NCH; c++) {
        int cur = c & 1;
        bool more = (c + 1 < NCH);
        if (more) {
            int kn = (c + 1) * BK;
            pa0 = *(const float4*)(aRow0 + kn);
            pa1 = *(const float4*)(aRow1 + kn);
            pb0 = *(const float4*)(bRow0 + kn);
            pb1 = *(const float4*)(bRow1 + kn);
        }
        const float* as = As[cur];
        const float* bs = Bs[cur];
#pragma unroll
        for (int k = 0; k < BK; k++) {
            ulonglong2 q0 = *(const ulonglong2*)&as[k * P1 + (ty << 4)];
            ulonglong2 q1 = *(const ulonglong2*)&as[k * P1 + (ty << 4) + 4];
            ulonglong2 q2 = *(const ulonglong2*)&as[k * P1 + (ty << 4) + 8];
            ulonglong2 q3 = *(const ulonglong2*)&as[k * P1 + (ty << 4) + 12];
            float4 bv = *(const float4*)&bs[k * P1 + (tx << 2)];
            unsigned long long bd0, bd1, bd2, bd3;
            asm("mov.b64 %0, {%1, %1};" : "=l"(bd0) : "f"(bv.x));
            asm("mov.b64 %0, {%1, %1};" : "=l"(bd1) : "f"(bv.y));
            asm("mov.b64 %0, {%1, %1};" : "=l"(bd2) : "f"(bv.z));
            asm("mov.b64 %0, {%1, %1};" : "=l"(bd3) : "f"(bv.w));
            unsigned long long ap[8] = {q0.x, q0.y, q1.x, q1.y, q2.x, q2.y, q3.x, q3.y};
#pragma unroll
            for (int p = 0; p < 8; p++) {
                asm("fma.rn.f32x2 %0, %1, %2, %0;" : "+l"(acc[p][0]) : "l"(ap[p]), "l"(bd0));
                asm("fma.rn.f32x2 %0, %1, %2, %0;" : "+l"(acc[p][1]) : "l"(ap[p]), "l"(bd1));
                asm("fma.rn.f32x2 %0, %1, %2, %0;" : "+l"(acc[p][2]) : "l"(ap[p]), "l"(bd2));
                asm("fma.rn.f32x2 %0, %1, %2, %0;" : "+l"(acc[p][3]) : "l"(ap[p]), "l"(bd3));
            }
        }
        if (more) {
            float* asn = As[cur ^ 1]; float* bsn = Bs[cur ^ 1];
            asn[(kk + 0) * P1 + r0] = pa0.x * iA0; asn[(kk + 1) * P1 + r0] = pa0.y * iA0;
            asn[(kk + 2) * P1 + r0] = pa0.z * iA0; asn[(kk + 3) * P1 + r0] = pa0.w * iA0;
            asn[(kk + 0) * P1 + r0 + 64] = pa1.x * iA1; asn[(kk + 1) * P1 + r0 + 64] = pa1.y * iA1;
            asn[(kk + 2) * P1 + r0 + 64] = pa1.z * iA1; asn[(kk + 3) * P1 + r0 + 64] = pa1.w * iA1;
            bsn[(kk + 0) * P1 + r0] = pb0.x * iB0; bsn[(kk + 1) * P1 + r0] = pb0.y * iB0;
            bsn[(kk + 2) * P1 + r0] = pb0.z * iB0; bsn[(kk + 3) * P1 + r0] = pb0.w * iB0;
            bsn[(kk + 0) * P1 + r0 + 64] = pb1.x * iB1; bsn[(kk + 1) * P1 + r0 + 64] = pb1.y * iB1;
            bsn[(kk + 2) * P1 + r0 + 64] = pb1.z * iB1; bsn[(kk + 3) * P1 + r0 + 64] = pb1.w * iB1;
        }
        __syncthreads();
    }

    int lcols[4];
#pragma unroll
    for (int j = 0; j < 4; j++) lcols[j] = labels[(tx << 2) + j];

#pragma unroll
    for (int p = 0; p < 8; p++) {
        float s[4][2];
#pragma unroll
        for (int j = 0; j < 4; j++)
            asm("mov.b64 {%0, %1}, %2;" : "=f"(s[j][0]), "=f"(s[j][1]) : "l"(acc[p][j]));
#pragma unroll
        for (int h = 0; h < 2; h++) {
            int lrow = (ty << 4) + (p << 1) + h;
            int arow = rowStart + lrow;
            float d = dg[arow];
            float m = mg[arow];
            int la = labels[arow];
            unsigned long long best = ~0ull;
#pragma unroll
            for (int j = 0; j < 4; j++) {
                float loss = s[j][h] - d + m;
                if (loss > 0.f && loss < m && lcols[j] != la) {
                    int cb = (tx << 2) + j;
                    unsigned long long key = ((unsigned long long)cb << 32) |
                                             (unsigned long long)__float_as_uint(loss);
                    best = umin64(best, key);
                }
            }
            if (best != ~0ull) atomicMin(&sbest[lrow], best);
        }
    }
    __syncthreads();
    if (tid < BM) {
        unsigned long long v = sbest[tid];
        int arow = rowStart + tid;
        g_best[pass][arow] = v;
        bool okm = (*aflag == 0) || (mg[arow] >= 0.16f);
        if (okm && v == ~0ull) {
            int p = atomicAdd(&g_cnt[pass], 1);
            g_list[pass][p] = arow;
        }
    }
}

// -------- kernel 3: phase-2a gathered 64x64 GEMM + fused collect2 tail ------
__global__ __launch_bounds__(256) void phase2a_kernel(
    const float* __restrict__ img, const float* __restrict__ txt,
    const float* __restrict__ cr, const float* __restrict__ margin,
    const int* __restrict__ labels) {
    __shared__ __align__(16) float As[2][BK2 * P2A];
    __shared__ __align__(16) float Bs[2][BK2 * P2A];
    __shared__ int sList[64];
    __shared__ unsigned long long sbest[64];
    __shared__ int sLast;

    int pass = blockIdx.y;
    const float *A, *Bm, *iA, *iB, *dg, *mg;
    pass_ptrs(pass, margin, img, txt, cr, A, Bm, iA, iB, dg, mg);
    int cnt = g_cnt[pass];

    int colStart = W1 + blockIdx.x * 64;
    int tid = threadIdx.x;
    int tx = tid & 15, tyy = tid >> 4;
    int sr = tid & 63;
    int sk = (tid >> 6) << 3;

    float iB0 = iB[colStart + sr];
    const float* bRow = Bm + (size_t)(colStart + sr) * DD + sk;

    for (int base = 0; base < cnt; base += 64) {
        __syncthreads();
        if (tid < 64) {
            int idx = base + tid;
            sList[tid] = (idx < cnt) ? g_list[pass][idx] : g_list[pass][0];
            sbest[tid] = ~0ull;
        }
        __syncthreads();

        unsigned long long acc[4][2];
#pragma unroll
        for (int i = 0; i < 4; i++) { acc[i][0] = 0ull; acc[i][1] = 0ull; }

        int arowr = sList[sr];
        float iA0 = iA[arowr];
        const float* aPtr = A + (size_t)arowr * DD + sk;

        float4 va0 = *(const float4*)aPtr;
        float4 va1 = *(const float4*)(aPtr + 4);
        float4 vb0 = *(const float4*)bRow;
        float4 vb1 = *(const float4*)(bRow + 4);

        {
            float* as = As[0]; float* bs = Bs[0];
            as[(sk + 0) * P2A + sr] = va0.x * iA0; as[(sk + 1) * P2A + sr] = va0.y * iA0;
            as[(sk + 2) * P2A + sr] = va0.z * iA0; as[(sk + 3) * P2A + sr] = va0.w * iA0;
            as[(sk + 4) * P2A + sr] = va1.x * iA0; as[(sk + 5) * P2A + sr] = va1.y * iA0;
            as[(sk + 6) * P2A + sr] = va1.z * iA0; as[(sk + 7) * P2A + sr] = va1.w * iA0;
            bs[(sk + 0) * P2A + sr] = vb0.x * iB0; bs[(sk + 1) * P2A + sr] = vb0.y * iB0;
            bs[(sk + 2) * P2A + sr] = vb0.z * iB0; bs[(sk + 3) * P2A + sr] = vb0.w * iB0;
            bs[(sk + 4) * P2A + sr] = vb1.x * iB0; bs[(sk + 5) * P2A + sr] = vb1.y * iB0;
            bs[(sk + 6) * P2A + sr] = vb1.z * iB0; bs[(sk + 7) * P2A + sr] = vb1.w * iB0;
        }
        __syncthreads();

        for (int c = 0; c < NCH2; c++) {
            int cur = c & 1;
            bool more = (c + 1 < NCH2);
            if (more) {
                int kn = (c + 1) * BK2;
                va0 = *(const float4*)(aPtr + kn);
                va1 = *(const float4*)(aPtr + kn + 4);
                vb0 = *(const float4*)(bRow + kn);
                vb1 = *(const float4*)(bRow + kn + 4);
            }
            const float* as = As[cur];
            const float* bs = Bs[cur];
#pragma unroll
            for (int k = 0; k < BK2; k++) {
                float4 a0 = *(const float4*)&as[k * P2A + (tyy << 2)];
                ulonglong2 b0 = *(const ulonglong2*)&bs[k * P2A + (tx << 2)];
                float af[4] = {a0.x, a0.y, a0.z, a0.w};
#pragma unroll
                for (int i = 0; i < 4; i++) {
                    unsigned long long aa;
                    asm("mov.b64 %0, {%1, %1};" : "=l"(aa) : "f"(af[i]));
                    asm("fma.rn.f32x2 %0, %1, %2, %0;" : "+l"(acc[i][0]) : "l"(aa), "l"(b0.x));
                    asm("fma.rn.f32x2 %0, %1, %2, %0;" : "+l"(acc[i][1]) : "l"(aa), "l"(b0.y));
                }
            }
            if (more) {
                float* asn = As[cur ^ 1]; float* bsn = Bs[cur ^ 1];
                asn[(sk + 0) * P2A + sr] = va0.x * iA0; asn[(sk + 1) * P2A + sr] = va0.y * iA0;
                asn[(sk + 2) * P2A + sr] = va0.z * iA0; asn[(sk + 3) * P2A + sr] = va0.w * iA0;
                asn[(sk + 4) * P2A + sr] = va1.x * iA0; asn[(sk + 5) * P2A + sr] = va1.y * iA0;
                asn[(sk + 6) * P2A + sr] = va1.z * iA0; asn[(sk + 7) * P2A + sr] = va1.w * iA0;
                bsn[(sk + 0) * P2A + sr] = vb0.x * iB0; bsn[(sk + 1) * P2A + sr] = vb0.y * iB0;
                bsn[(sk + 2) * P2A + sr] = vb0.z * iB0; bsn[(sk + 3) * P2A + sr] = vb0.w * iB0;
                bsn[(sk + 4) * P2A + sr] = vb1.x * iB0; bsn[(sk + 5) * P2A + sr] = vb1.y * iB0;
                bsn[(sk + 6) * P2A + sr] = vb1.z * iB0; bsn[(sk + 7) * P2A + sr] = vb1.w * iB0;
            }
            __syncthreads();
        }

#pragma unroll
        for (int i = 0; i < 4; i++) {
            int lr = (tyy << 2) + i;
            if (base + lr >= cnt) continue;
            int arow = sList[lr];
            float d = dg[arow];
            float m = mg[arow];
            int la = labels[arow];
            unsigned long long best = ~0ull;
#pragma unroll
            for (int jp = 0; jp < 2; jp++) {
                float lo, hi;
                asm("mov.b64 {%0, %1}, %2;" : "=f"(lo), "=f"(hi) : "l"(acc[i][jp]));
                int cb = colStart + (tx << 2) + (jp << 1);
                float loss0 = lo - d + m;
                float loss1 = hi - d + m;
                if (loss0 > 0.f && loss0 < m && labels[cb] != la) {
                    unsigned long long key = ((unsigned long long)cb << 32) |
                                             (unsigned long long)__float_as_uint(loss0);
                    best = umin64(best, key);
                }
                if (loss1 > 0.f && loss1 < m && labels[cb + 1] != la) {
                    unsigned long long key = ((unsigned long long)(cb + 1) << 32) |
                                             (unsigned long long)__float_as_uint(loss1);
                    best = umin64(best, key);
                }
            }
            if (best != ~0ull) atomicMin(&sbest[lr], best);
        }
        __syncthreads();
        if (tid < 64 && base + tid < cnt && sbest[tid] != ~0ull)
            atomicMin(&g_best[pass][sList[tid]], sbest[tid]);
    }

    // fused collect2: last CTA of this pass scans the (small) stage-1 list
    __syncthreads();
    if (tid == 0) {
        __threadfence();
        sLast = (atomicAdd(&g_tick2a[pass], 1) == (int)gridDim.x - 1) ? 1 : 0;
    }
    __syncthreads();
    if (sLast) {
        __threadfence();
        for (int i = tid; i < cnt; i += 256) {
            int a = g_list[pass][i];
            if (__ldcg(&g_best[pass][a]) == ~0ull) {
                int p = atomicAdd(&g_cnt2[pass], 1);
                g_list2[pass][p] = a;
            }
        }
    }
}

// -------- kernel 4: phase-2b warp-per-column-pair + fused final tail --------
// 16 columns per CTA (2 per warp); anchors smem-staged, lanes split the k dim.
__global__ __launch_bounds__(256) void phase2b_kernel(
    const float* __restrict__ img, const float* __restrict__ txt,
    const float* __restrict__ cr, const float* __restrict__ margin,
    const int* __restrict__ labels, const int* __restrict__ aflag,
    const float* __restrict__ crbeta, float* __restrict__ out) {
    __shared__ __align__(16) float sA[MAXA][DD];   // 16 KB pre-scaled anchor rows
    __shared__ float sd[MAXA], smg[MAXA];
    __shared__ int sLab[MAXA], sIdx[MAXA];
    __shared__ int sLast;
    __shared__ double sh1[256], sh2[256];

    int pass = blockIdx.y;
    const float *A, *Bm, *iA, *iB, *dg, *mg;
    pass_ptrs(pass, margin, img, txt, cr, A, Bm, iA, iB, dg, mg);
    int cnt2 = g_cnt2[pass];

    int tid = threadIdx.x;
    int wid = tid >> 5, lane = tid & 31;
    int col0 = W1 + W2 + blockIdx.x * 16 + wid * 2;
    int col1 = col0 + 1;

    if (cnt2 > 0) {
        float iB0 = iB[col0], iB1 = iB[col1];
        int lc0 = labels[col0], lc1 = labels[col1];
        const float4* br0 = (const float4*)(Bm + (size_t)col0 * DD);
        const float4* br1 = (const float4*)(Bm + (size_t)col1 * DD);
        float4 b0[4], b1[4];
#pragma unroll
        for (int e = 0; e < 4; e++) {
            b0[e] = br0[lane + 32 * e];
            b1[e] = br1[lane + 32 * e];
        }

        for (int base = 0; base < cnt2; base += MAXA) {
            __syncthreads();   // guard smem reuse
            for (int q = tid; q < MAXA * (DD / 4); q += 256) {
                int anc = q >> 7;
                int e = q & 127;
                int idx = base + anc;
                int a = g_list2[pass][idx < cnt2 ? idx : base];
                float iA0 = iA[a];
                float4 v = ((const float4*)(A + (size_t)a * DD))[e];
                ((float4*)sA[anc])[e] = make_float4(v.x * iA0, v.y * iA0, v.z * iA0, v.w * iA0);
            }
            if (tid < MAXA) {
                int idx = base + tid;
                int a = g_list2[pass][idx < cnt2 ? idx : base];
                sIdx[tid] = a;
                sd[tid] = dg[a];
                smg[tid] = mg[a];
                sLab[tid] = labels[a];
            }
            __syncthreads();

            float acc0[MAXA], acc1[MAXA];
#pragma unroll
            for (int i = 0; i < MAXA; i++) { acc0[i] = 0.f; acc1[i] = 0.f; }
#pragma unroll
            for (int e = 0; e < 4; e++) {
#pragma unroll
                for (int anc = 0; anc < MAXA; anc++) {
                    float4 av = ((const float4*)sA[anc])[lane + 32 * e];
                    acc0[anc] += b0[e].x * av.x + b0[e].y * av.y +
                                 b0[e].z * av.z + b0[e].w * av.w;
                    acc1[anc] += b1[e].x * av.x + b1[e].y * av.y +
                                 b1[e].z * av.z + b1[e].w * av.w;
                }
            }
#pragma unroll
            for (int off = 16; off; off >>= 1) {
#pragma unroll
                for (int anc = 0; anc < MAXA; anc++) {
                    acc0[anc] += __shfl_xor_sync(0xFFFFFFFFu, acc0[anc], off);
                    acc1[anc] += __shfl_xor_sync(0xFFFFFFFFu, acc1[anc], off);
                }
            }
            if (lane == 0) {
#pragma unroll
                for (int anc = 0; anc < MAXA; anc++) {
                    if (base + anc >= cnt2) break;
                    float m = smg[anc];
                    float d = sd[anc];
                    int la = sLab[anc];
                    float loss0 = acc0[anc] * iB0 - d + m;
                    float loss1 = acc1[anc] * iB1 - d + m;
                    unsigned long long best = ~0ull;
                    if (loss0 > 0.f && loss0 < m && lc0 != la) {
                        unsigned long long key = ((unsigned long long)col0 << 32) |
                                                 (unsigned long long)__float_as_uint(loss0);
                        best = umin64(best, key);
                    }
                    if (loss1 > 0.f && loss1 < m && lc1 != la) {
                        unsigned long long key = ((unsigned long long)col1 << 32) |
                                                 (unsigned long long)__float_as_uint(loss1);
                        best = umin64(best, key);
                    }
                    if (best != ~0ull) atomicMin(&g_best[pass][sIdx[anc]], best);
                }
            }
        }
    }

    // fused final reduction: globally last CTA sums all mined losses
    __syncthreads();
    if (tid == 0) {
        __threadfence();
        int totalCtas = (int)(gridDim.x * gridDim.y);
        sLast = (atomicAdd(&g_tickb, 1) == totalCtas - 1) ? 1 : 0;
    }
    __syncthreads();
    if (sLast) {
        __threadfence();
        int af = *aflag;
        double s1 = 0.0, s2 = 0.0;
        for (int a = tid; a < BB; a += 256) {
            bool okb = af ? (margin[a] >= 0.16f) : true;
            bool okc = af ? (g_mcr[a] >= 0.16f) : true;
            unsigned long long v;
            v = __ldcg(&g_best[0][a]);
            if (okb && v != ~0ull) s1 += (double)__uint_as_float((unsigned)v);
            v = __ldcg(&g_best[1][a]);
            if (okb && v != ~0ull) s1 += (double)__uint_as_float((unsigned)v);
            v = __ldcg(&g_best[2][a]);
            if (okc && v != ~0ull) s2 += (double)__uint_as_float((unsigned)v);
            v = __ldcg(&g_best[3][a]);
            if (okc && v != ~0ull) s2 += (double)__uint_as_float((unsigned)v);
        }
        sh1[tid] = s1; sh2[tid] = s2;
        __syncthreads();
        for (int s = 128; s; s >>= 1) {
            if (tid < s) { sh1[tid] += sh1[tid + s]; sh2[tid] += sh2[tid + s]; }
            __syncthreads();
        }
        if (tid == 0) out[0] = (float)(sh1[0] + (double)crbeta[0] * sh2[0]);
    }
}

extern "C" void kernel_launch(void* const* d_in, const int* in_sizes, int n_in,
                              void* d_out, int out_size) {
    const float* img    = (const float*)d_in[0];
    const float* txt    = (const float*)d_in[1];
    const float* txtcr  = (const float*)d_in[2];
    const int*   labels = (const int*)d_in[3];
    const int*   aflag  = (const int*)d_in[4];
    const float* margin = (const float*)d_in[5];
    const float* crbeta = (const float*)d_in[6];
    float* out = (float*)d_out;

    prep_kernel<<<BB / 8, 256>>>(img, txt, txtcr, margin, aflag);
    phase1_kernel<<<dim3(BB / BM, 4), 256>>>(img, txt, txtcr, margin, labels, aflag);
    phase2a_kernel<<<dim3(W2 / 64, 4), 256>>>(img, txt, txtcr, margin, labels);
    phase2b_kernel<<<dim3((BB - W1 - W2) / 16, 4), 256>>>(img, txt, txtcr, margin,
                                                          labels, aflag, crbeta, out);
}